// round 7
// baseline (speedup 1.0000x reference)
#include <cuda_runtime.h>

#define BB   4
#define CIN  64
#define COUT 64
#define NPTS 8192
#define KNN  16
#define NQ   (BB * NPTS)
#define CAP  192
#define SAMP 1024
#define TCB  1024   // candidates per collect tile (512 pairs)

// Static scratch (no runtime allocation allowed)
__device__ int   g_idx[NQ * KNN];   // [q][k]      2 MB
__device__ float g_z[NQ * COUT];    // zT[b][n][o] 8 MB
__device__ float g_thr[NQ];         // per-query threshold
__device__ int   g_wcount;          // fallback worklist size
__device__ int   g_wlist[NQ];       // fallback worklist

// --------------------------- f32x2 helpers ---------------------------------
__device__ __forceinline__ unsigned long long pk2(float lo, float hi) {
    unsigned long long r;
    asm("mov.b64 %0, {%1, %2};" : "=l"(r) : "f"(lo), "f"(hi));
    return r;
}
__device__ __forceinline__ void upk2(unsigned long long v, float& lo, float& hi) {
    asm("mov.b64 {%0, %1}, %2;" : "=f"(lo), "=f"(hi) : "l"(v));
}
__device__ __forceinline__ unsigned long long mul2(unsigned long long a, unsigned long long b) {
    unsigned long long r;
    asm("mul.rn.f32x2 %0, %1, %2;" : "=l"(r) : "l"(a), "l"(b));
    return r;
}
__device__ __forceinline__ unsigned long long add2(unsigned long long a, unsigned long long b) {
    unsigned long long r;
    asm("add.rn.f32x2 %0, %1, %2;" : "=l"(r) : "l"(a), "l"(b));
    return r;
}
__device__ __forceinline__ unsigned long long fma2(unsigned long long a, unsigned long long b,
                                                   unsigned long long c) {
    unsigned long long r;
    asm("fma.rn.f32x2 %0, %1, %2, %3;" : "=l"(r) : "l"(a), "l"(b), "l"(c));
    return r;
}

// ---------------------------------------------------------------------------
// Threshold: 8th smallest distance over a stride-8 1024-point subsample.
// (Separate kernel — R4 configuration; fusing this regressed in R5.)
// ---------------------------------------------------------------------------
__global__ void __launch_bounds__(128) knn_thresh(const float* __restrict__ coords) {
    __shared__ float4 sp[SAMP];
    int tid = threadIdx.x;
    int b   = blockIdx.x >> 6;                  // 64 blocks per batch
    const float* cb = coords + b * 3 * NPTS;

    for (int t = tid; t < SAMP; t += 128) {
        int j = t * 8;
        float cx = cb[j], cy = cb[NPTS + j], cz = cb[2 * NPTS + j];
        sp[t] = make_float4(cx, cy, cz, (cx * cx + cy * cy) + cz * cz);
    }
    __syncthreads();

    int q = blockIdx.x * 128 + tid;
    int n = q & (NPTS - 1);
    float qx = cb[n], qy = cb[NPTS + n], qz = cb[2 * NPTS + n];
    float sqi = (qx * qx + qy * qy) + qz * qz;

    float t8[8];
#pragma unroll
    for (int s = 0; s < 8; s++) t8[s] = __int_as_float(0x7f800000);

#pragma unroll 4
    for (int t = 0; t < SAMP; t++) {
        float4 c = sp[t];
        float inner = fmaf(qz, c.z, fmaf(qy, c.y, qx * c.x));
        float d = fmaf(-2.0f, inner, sqi + c.w);
        if (d < t8[7]) {
            float v = d;
#pragma unroll
            for (int s = 0; s < 8; s++) {
                float lo = fminf(t8[s], v);
                float hi = fmaxf(t8[s], v);
                t8[s] = lo; v = hi;
            }
        }
    }
    g_thr[q] = t8[7];
}

// ---------------------------------------------------------------------------
// Collect (R4 configuration, byte-identical hot loop): full scan with packed
// f32x2 math; hits d<=T into a per-thread LOCAL buffer; exact top-16 from
// the buffer. Rare bad queries appended to the fallback worklist.
// ---------------------------------------------------------------------------
__global__ void __launch_bounds__(128) knn_collect(const float* __restrict__ coords) {
    __shared__ float4 sxy[TCB / 2];   // (x0,x1,y0,y1) per pair
    __shared__ float4 szw[TCB / 2];   // (z0,z1,sq0,sq1) per pair

    unsigned long long buf[CAP];      // per-thread local (stack)

    int tid = threadIdx.x;
    int q   = blockIdx.x * 128 + tid;
    int b   = blockIdx.x >> 6;
    int n   = q & (NPTS - 1);
    const float* cb = coords + b * 3 * NPTS;

    float qx = cb[n], qy = cb[NPTS + n], qz = cb[2 * NPTS + n];
    float sqi = (qx * qx + qy * qy) + qz * qz;

    unsigned long long qx2 = pk2(qx, qx), qy2 = pk2(qy, qy), qz2 = pk2(qz, qz);
    unsigned long long sq2 = pk2(sqi, sqi);
    unsigned long long m2  = pk2(-2.0f, -2.0f);

    float T = g_thr[q];
    int cnt = 0;

    for (int tb = 0; tb < NPTS; tb += TCB) {
        __syncthreads();
        float* fxy = (float*)sxy;
        float* fzw = (float*)szw;
        for (int e = tid; e < TCB; e += 128) {
            int j = tb + e;
            float cx = cb[j], cy = cb[NPTS + j], cz = cb[2 * NPTS + j];
            int p = e >> 1, o = e & 1;
            fxy[p * 4 + o]     = cx;
            fxy[p * 4 + 2 + o] = cy;
            fzw[p * 4 + o]     = cz;
            fzw[p * 4 + 2 + o] = (cx * cx + cy * cy) + cz * cz;
        }
        __syncthreads();

#pragma unroll 8
        for (int p = 0; p < TCB / 2; p++) {
            float4 a  = sxy[p];
            float4 zz = szw[p];
            unsigned long long x01 = pk2(a.x, a.y),  y01 = pk2(a.z, a.w);
            unsigned long long z01 = pk2(zz.x, zz.y), w01 = pk2(zz.z, zz.w);
            unsigned long long t0 = mul2(qx2, x01);
            t0 = fma2(qy2, y01, t0);
            t0 = fma2(qz2, z01, t0);
            unsigned long long d2 = fma2(m2, t0, add2(sq2, w01));
            float d0, d1;
            upk2(d2, d0, d1);
            if (fminf(d0, d1) <= T) {
                int j0 = tb + 2 * p;
                if (d0 <= T && cnt < CAP) {
                    buf[cnt] = ((unsigned long long)(unsigned)j0 << 32) | __float_as_uint(d0);
                    cnt++;
                }
                if (d1 <= T && cnt < CAP) {
                    buf[cnt] = ((unsigned long long)(unsigned)(j0 + 1) << 32) | __float_as_uint(d1);
                    cnt++;
                }
            }
        }
    }

    // Exact top-16 from buffered candidates (ascending-j order + strict-less
    // insertion reproduces top_k's lowest-index tie-break).
    float ds[KNN];
    int   is_[KNN];
#pragma unroll
    for (int s = 0; s < KNN; s++) { ds[s] = __int_as_float(0x7f800000); is_[s] = 0; }

    for (int t = 0; t < cnt; t++) {
        unsigned long long e = buf[t];
        float d = __uint_as_float((unsigned)e);
        int   j = (int)(e >> 32);
        if (d < ds[KNN - 1]) {
            float vd = d; int vi = j;
#pragma unroll
            for (int s = 0; s < KNN; s++) {
                float od = ds[s]; int oi = is_[s];
                bool  pr = vd < od;
                ds[s]  = pr ? vd : od;
                is_[s] = pr ? vi : oi;
                vd     = pr ? od : vd;
                vi     = pr ? oi : vi;
            }
        }
    }

    int* op = g_idx + q * KNN;
#pragma unroll
    for (int s = 0; s < KNN; s++) op[s] = is_[s];

    // cnt saturates at CAP: cnt==CAP may mean overflow -> fall back too.
    if (cnt < KNN || cnt >= CAP) {
        int slot = atomicAdd(&g_wcount, 1);
        g_wlist[slot] = q;
    }
}

// ---------------------------------------------------------------------------
// Fallback: worklist-driven warp-cooperative exact scan (R5 configuration).
// ---------------------------------------------------------------------------
__global__ void __launch_bounds__(32) knn_fallback(const float* __restrict__ coords) {
    int lane = threadIdx.x;
    int nw = g_wcount;

    for (int w = blockIdx.x; w < nw; w += 256) {
        int q = g_wlist[w];
        int b = q >> 13, n = q & (NPTS - 1);
        const float* cb = coords + b * 3 * NPTS;
        float qx = cb[n], qy = cb[NPTS + n], qz = cb[2 * NPTS + n];
        float sqi = (qx * qx + qy * qy) + qz * qz;

        float ds[KNN];
        int   is_[KNN];
#pragma unroll
        for (int s = 0; s < KNN; s++) { ds[s] = __int_as_float(0x7f800000); is_[s] = 0x7fffffff; }

        for (int i = 0; i < NPTS / 32; i++) {
            int j = i * 32 + lane;
            float cx = cb[j], cy = cb[NPTS + j], cz = cb[2 * NPTS + j];
            float sq = (cx * cx + cy * cy) + cz * cz;
            float inner = fmaf(qz, cz, fmaf(qy, cy, qx * cx));
            float d = fmaf(-2.0f, inner, sqi + sq);
            if (d < ds[KNN - 1]) {
                float vd = d; int vi = j;
#pragma unroll
                for (int s = 0; s < KNN; s++) {
                    float od = ds[s]; int oi = is_[s];
                    bool  pr = vd < od;
                    ds[s]  = pr ? vd : od;
                    is_[s] = pr ? vi : oi;
                    vd     = pr ? od : vd;
                    vi     = pr ? oi : vi;
                }
            }
        }

        __shared__ float sd[32][KNN];
        __shared__ int   sj[32][KNN];
#pragma unroll
        for (int s = 0; s < KNN; s++) { sd[lane][s] = ds[s]; sj[lane][s] = is_[s]; }
        __syncwarp();

        int ptr = 0;
        for (int k = 0; k < KNN; k++) {
            float cd = (ptr < KNN) ? sd[lane][ptr] : __int_as_float(0x7f800000);
            int   cj = (ptr < KNN) ? sj[lane][ptr] : 0x7fffffff;
            float wd = cd; int wj = cj;
#pragma unroll
            for (int off = 16; off > 0; off >>= 1) {
                float od = __shfl_xor_sync(0xffffffffu, wd, off);
                int   oj = __shfl_xor_sync(0xffffffffu, wj, off);
                if (od < wd || (od == wd && oj < wj)) { wd = od; wj = oj; }
            }
            if (wd == cd && wj == cj) ptr++;
            if (lane == 0) g_idx[q * KNN + k] = wj;
        }
        __syncwarp();
    }
}

// ---------------------------------------------------------------------------
// GEMM: z[b][n][o] = sum_c W[o][c] * x[b][c][n]; zeroes worklist counter.
// ---------------------------------------------------------------------------
__global__ void __launch_bounds__(128) gemm_kernel(const float* __restrict__ x,
                                                   const float* __restrict__ W) {
    if (blockIdx.x == 0 && threadIdx.x == 0) g_wcount = 0;

    __shared__ float ws[COUT * CIN];
    int tid = threadIdx.x;
#pragma unroll
    for (int u = 0; u < 8; u++)
        ((float4*)ws)[tid + u * 128] = ((const float4*)W)[tid + u * 128];
    __syncthreads();

    int b     = blockIdx.x >> 7;
    int ntile = (blockIdx.x & 127) * 64;
    int nl    = tid & 63;
    int o0    = (tid >> 6) * 32;
    int n     = ntile + nl;

    const float* xb = x + b * CIN * NPTS;

    float acc[32];
#pragma unroll
    for (int i = 0; i < 32; i++) acc[i] = 0.0f;

    for (int c = 0; c < CIN; c += 4) {
        float xv0 = xb[(c + 0) * NPTS + n];
        float xv1 = xb[(c + 1) * NPTS + n];
        float xv2 = xb[(c + 2) * NPTS + n];
        float xv3 = xb[(c + 3) * NPTS + n];
#pragma unroll
        for (int i = 0; i < 32; i++) {
            float4 w4 = *(const float4*)&ws[(o0 + i) * CIN + c];
            acc[i] = fmaf(w4.x, xv0, acc[i]);
            acc[i] = fmaf(w4.y, xv1, acc[i]);
            acc[i] = fmaf(w4.z, xv2, acc[i]);
            acc[i] = fmaf(w4.w, xv3, acc[i]);
        }
    }

    float* zp = g_z + ((size_t)b * NPTS + n) * COUT + o0;
#pragma unroll
    for (int i = 0; i < 32; i += 4)
        *(float4*)&zp[i] = make_float4(acc[i], acc[i + 1], acc[i + 2], acc[i + 3]);
}

// ---------------------------------------------------------------------------
// Max-gather + coords passthrough (tail blocks) — R5 configuration,
// measured 16.2 us including the copy.
// ---------------------------------------------------------------------------
#define MG_BLOCKS   (BB * 256)
#define CP_FLOAT4   (BB * 3 * NPTS / 4)
#define CP_BLOCKS   (CP_FLOAT4 / 256)

__global__ void __launch_bounds__(256) maxgather_kernel(float* __restrict__ y,
                                                        const float* __restrict__ coords) {
    if (blockIdx.x >= MG_BLOCKS) {
        int i = (blockIdx.x - MG_BLOCKS) * 256 + threadIdx.x;
        float4* dst = (float4*)(y + (size_t)BB * COUT * NPTS);
        dst[i] = ((const float4*)coords)[i];
        return;
    }

    __shared__ float yt[COUT][33];

    int tid = threadIdx.x;
    int w   = tid >> 5;
    int l   = tid & 31;
    int b     = blockIdx.x >> 8;
    int ntile = (blockIdx.x & 255) * 32;

    const float* zb = g_z + (size_t)b * NPTS * COUT;
    const float NEG_INF = __int_as_float(0xff800000);

    for (int qq = 0; qq < 4; qq++) {
        int nl = w * 4 + qq;
        int n  = ntile + nl;
        const int* ip = g_idx + ((size_t)b * NPTS + n) * KNN;
        float m0 = NEG_INF, m1 = NEG_INF;
#pragma unroll
        for (int k = 0; k < KNN; k++) {
            int r = __ldg(&ip[k]);
            const float* zr = zb + (size_t)r * COUT;
            m0 = fmaxf(m0, zr[l]);
            m1 = fmaxf(m1, zr[l + 32]);
        }
        yt[l][nl]      = m0;
        yt[l + 32][nl] = m1;
    }
    __syncthreads();

#pragma unroll
    for (int e = tid; e < COUT * 32; e += 256) {
        int o  = e >> 5;
        int nl = e & 31;
        y[((size_t)b * COUT + o) * NPTS + ntile + nl] = yt[o][nl];
    }
}

// ---------------------------------------------------------------------------
extern "C" void kernel_launch(void* const* d_in, const int* in_sizes, int n_in,
                              void* d_out, int out_size) {
    const float* x      = (const float*)d_in[0];
    const float* coords = (const float*)d_in[1];
    const float* W      = (const float*)d_in[2];
    float*       out    = (float*)d_out;

    gemm_kernel<<<BB * 128, 128>>>(x, W);
    knn_thresh<<<NQ / 128, 128>>>(coords);
    knn_collect<<<NQ / 128, 128>>>(coords);
    knn_fallback<<<256, 32>>>(coords);
    maxgather_kernel<<<MG_BLOCKS + CP_BLOCKS, 256>>>(out, coords);
}

// round 8
// speedup vs baseline: 1.2665x; 1.2665x over previous
#include <cuda_runtime.h>

#define BB   4
#define CIN  64
#define COUT 64
#define NPTS 8192
#define KNN  16
#define NQ   (BB * NPTS)
#define CAP  192
#define SAMP 1024
#define TCB  1024   // candidates per collect tile (512 pairs)

// Static scratch (no runtime allocation allowed)
__device__ int                g_idx[NQ * KNN];          // [q][k]
__device__ float              g_z[NQ * COUT];           // zT[b][n][o]
__device__ float              g_thr[NQ];                // per-query threshold
__device__ unsigned long long g_buf[(size_t)NQ * CAP];  // hits: (j<<32)|d  (R3 config)
__device__ int                g_wcount;                 // fallback worklist size
__device__ int                g_wlist[NQ];

// --------------------------- f32x2 helpers ---------------------------------
__device__ __forceinline__ unsigned long long pk2(float lo, float hi) {
    unsigned long long r;
    asm("mov.b64 %0, {%1, %2};" : "=l"(r) : "f"(lo), "f"(hi));
    return r;
}
__device__ __forceinline__ void upk2(unsigned long long v, float& lo, float& hi) {
    asm("mov.b64 {%0, %1}, %2;" : "=f"(lo), "=f"(hi) : "l"(v));
}
__device__ __forceinline__ unsigned long long mul2(unsigned long long a, unsigned long long b) {
    unsigned long long r;
    asm("mul.rn.f32x2 %0, %1, %2;" : "=l"(r) : "l"(a), "l"(b));
    return r;
}
__device__ __forceinline__ unsigned long long add2(unsigned long long a, unsigned long long b) {
    unsigned long long r;
    asm("add.rn.f32x2 %0, %1, %2;" : "=l"(r) : "l"(a), "l"(b));
    return r;
}
__device__ __forceinline__ unsigned long long fma2(unsigned long long a, unsigned long long b,
                                                   unsigned long long c) {
    unsigned long long r;
    asm("fma.rn.f32x2 %0, %1, %2, %3;" : "=l"(r) : "l"(a), "l"(b), "l"(c));
    return r;
}

// ---------------------------------------------------------------------------
// Threshold: 8th smallest distance over a stride-8 1024-point subsample.
// ---------------------------------------------------------------------------
__global__ void __launch_bounds__(128) knn_thresh(const float* __restrict__ coords) {
    __shared__ float4 sp[SAMP];
    int tid = threadIdx.x;
    int b   = blockIdx.x >> 6;                  // 64 blocks per batch
    const float* cb = coords + b * 3 * NPTS;

    for (int t = tid; t < SAMP; t += 128) {
        int j = t * 8;
        float cx = cb[j], cy = cb[NPTS + j], cz = cb[2 * NPTS + j];
        sp[t] = make_float4(cx, cy, cz, (cx * cx + cy * cy) + cz * cz);
    }
    __syncthreads();

    int q = blockIdx.x * 128 + tid;
    int n = q & (NPTS - 1);
    float qx = cb[n], qy = cb[NPTS + n], qz = cb[2 * NPTS + n];
    float sqi = (qx * qx + qy * qy) + qz * qz;

    float t8[8];
#pragma unroll
    for (int s = 0; s < 8; s++) t8[s] = __int_as_float(0x7f800000);

#pragma unroll 4
    for (int t = 0; t < SAMP; t++) {
        float4 c = sp[t];
        float inner = fmaf(qz, c.z, fmaf(qy, c.y, qx * c.x));
        float d = fmaf(-2.0f, inner, sqi + c.w);
        if (d < t8[7]) {
            float v = d;
#pragma unroll
            for (int s = 0; s < 8; s++) {
                float lo = fminf(t8[s], v);
                float hi = fmaxf(t8[s], v);
                t8[s] = lo; v = hi;
            }
        }
    }
    g_thr[q] = t8[7];
}

// ---------------------------------------------------------------------------
// Collect (R3 configuration — GLOBAL per-query buffer, the measured-fast one):
// full scan with packed f32x2 math; hits d<=T appended to g_buf; exact top-16
// bubble over the buffer inline. Rare bad queries -> worklist.
// ---------------------------------------------------------------------------
__global__ void __launch_bounds__(128) knn_collect(const float* __restrict__ coords) {
    __shared__ float4 sxy[TCB / 2];   // (x0,x1,y0,y1) per pair
    __shared__ float4 szw[TCB / 2];   // (z0,z1,sq0,sq1) per pair

    int tid = threadIdx.x;
    int q   = blockIdx.x * 128 + tid;
    int b   = blockIdx.x >> 6;
    int n   = q & (NPTS - 1);
    const float* cb = coords + b * 3 * NPTS;

    float qx = cb[n], qy = cb[NPTS + n], qz = cb[2 * NPTS + n];
    float sqi = (qx * qx + qy * qy) + qz * qz;

    unsigned long long qx2 = pk2(qx, qx), qy2 = pk2(qy, qy), qz2 = pk2(qz, qz);
    unsigned long long sq2 = pk2(sqi, sqi);
    unsigned long long m2  = pk2(-2.0f, -2.0f);

    float T = g_thr[q];
    int cnt = 0;
    size_t base = (size_t)q * CAP;

    for (int tb = 0; tb < NPTS; tb += TCB) {
        __syncthreads();
        float* fxy = (float*)sxy;
        float* fzw = (float*)szw;
        for (int e = tid; e < TCB; e += 128) {
            int j = tb + e;
            float cx = cb[j], cy = cb[NPTS + j], cz = cb[2 * NPTS + j];
            int p = e >> 1, o = e & 1;
            fxy[p * 4 + o]     = cx;
            fxy[p * 4 + 2 + o] = cy;
            fzw[p * 4 + o]     = cz;
            fzw[p * 4 + 2 + o] = (cx * cx + cy * cy) + cz * cz;
        }
        __syncthreads();

#pragma unroll 8
        for (int p = 0; p < TCB / 2; p++) {
            float4 a  = sxy[p];
            float4 zz = szw[p];
            unsigned long long x01 = pk2(a.x, a.y),  y01 = pk2(a.z, a.w);
            unsigned long long z01 = pk2(zz.x, zz.y), w01 = pk2(zz.z, zz.w);
            unsigned long long t0 = mul2(qx2, x01);
            t0 = fma2(qy2, y01, t0);
            t0 = fma2(qz2, z01, t0);
            unsigned long long d2 = fma2(m2, t0, add2(sq2, w01));
            float d0, d1;
            upk2(d2, d0, d1);
            if (fminf(d0, d1) <= T) {
                int j0 = tb + 2 * p;
                if (d0 <= T) {
                    if (cnt < CAP)
                        g_buf[base + cnt] =
                            ((unsigned long long)(unsigned)j0 << 32) | __float_as_uint(d0);
                    cnt++;
                }
                if (d1 <= T) {
                    if (cnt < CAP)
                        g_buf[base + cnt] =
                            ((unsigned long long)(unsigned)(j0 + 1) << 32) | __float_as_uint(d1);
                    cnt++;
                }
            }
        }
    }

    // Exact top-16 from buffered candidates (ascending-j order + strict-less
    // insertion reproduces top_k's lowest-index tie-break).
    int m = cnt < CAP ? cnt : CAP;
    float ds[KNN];
    int   is_[KNN];
#pragma unroll
    for (int s = 0; s < KNN; s++) { ds[s] = __int_as_float(0x7f800000); is_[s] = 0; }

    for (int t = 0; t < m; t++) {
        unsigned long long e = g_buf[base + t];
        float d = __uint_as_float((unsigned)e);
        int   j = (int)(e >> 32);
        if (d < ds[KNN - 1]) {
            float vd = d; int vi = j;
#pragma unroll
            for (int s = 0; s < KNN; s++) {
                float od = ds[s]; int oi = is_[s];
                bool  pr = vd < od;
                ds[s]  = pr ? vd : od;
                is_[s] = pr ? vi : oi;
                vd     = pr ? od : vd;
                vi     = pr ? oi : vi;
            }
        }
    }

    int* op = g_idx + q * KNN;
#pragma unroll
    for (int s = 0; s < KNN; s++) op[s] = is_[s];

    if (cnt < KNN || cnt > CAP) {
        int slot = atomicAdd(&g_wcount, 1);
        g_wlist[slot] = q;
    }
}

// ---------------------------------------------------------------------------
// Fallback: worklist-driven warp-cooperative exact scan, now UNROLLED x8
// with front-batched loads (MLP~24) to kill the serial load-latency chain
// that cost 218us in R7. Same math, same lane order, same warp merge.
// ---------------------------------------------------------------------------
__global__ void __launch_bounds__(32) knn_fallback(const float* __restrict__ coords) {
    int lane = threadIdx.x;
    int nw = g_wcount;

    for (int w = blockIdx.x; w < nw; w += 256) {
        int q = g_wlist[w];
        int b = q >> 13, n = q & (NPTS - 1);
        const float* cb = coords + b * 3 * NPTS;
        float qx = cb[n], qy = cb[NPTS + n], qz = cb[2 * NPTS + n];
        float sqi = (qx * qx + qy * qy) + qz * qz;

        float ds[KNN];
        int   is_[KNN];
#pragma unroll
        for (int s = 0; s < KNN; s++) { ds[s] = __int_as_float(0x7f800000); is_[s] = 0x7fffffff; }

        for (int i = 0; i < NPTS / 32; i += 8) {
            float cxs[8], cys[8], czs[8];
#pragma unroll
            for (int u = 0; u < 8; u++) {
                int j = (i + u) * 32 + lane;
                cxs[u] = __ldg(cb + j);
                cys[u] = __ldg(cb + NPTS + j);
                czs[u] = __ldg(cb + 2 * NPTS + j);
            }
#pragma unroll
            for (int u = 0; u < 8; u++) {
                int j = (i + u) * 32 + lane;
                float sq = (cxs[u] * cxs[u] + cys[u] * cys[u]) + czs[u] * czs[u];
                float inner = fmaf(qz, czs[u], fmaf(qy, cys[u], qx * cxs[u]));
                float d = fmaf(-2.0f, inner, sqi + sq);
                if (d < ds[KNN - 1]) {
                    float vd = d; int vi = j;
#pragma unroll
                    for (int s = 0; s < KNN; s++) {
                        float od = ds[s]; int oi = is_[s];
                        bool  pr = vd < od;
                        ds[s]  = pr ? vd : od;
                        is_[s] = pr ? vi : oi;
                        vd     = pr ? od : vd;
                        vi     = pr ? oi : vi;
                    }
                }
            }
        }

        __shared__ float sd[32][KNN];
        __shared__ int   sj[32][KNN];
#pragma unroll
        for (int s = 0; s < KNN; s++) { sd[lane][s] = ds[s]; sj[lane][s] = is_[s]; }
        __syncwarp();

        int ptr = 0;
        for (int k = 0; k < KNN; k++) {
            float cd = (ptr < KNN) ? sd[lane][ptr] : __int_as_float(0x7f800000);
            int   cj = (ptr < KNN) ? sj[lane][ptr] : 0x7fffffff;
            float wd = cd; int wj = cj;
#pragma unroll
            for (int off = 16; off > 0; off >>= 1) {
                float od = __shfl_xor_sync(0xffffffffu, wd, off);
                int   oj = __shfl_xor_sync(0xffffffffu, wj, off);
                if (od < wd || (od == wd && oj < wj)) { wd = od; wj = oj; }
            }
            if (wd == cd && wj == cj) ptr++;
            if (lane == 0) g_idx[q * KNN + k] = wj;
        }
        __syncwarp();
    }
}

// ---------------------------------------------------------------------------
// GEMM: z[b][n][o] = sum_c W[o][c] * x[b][c][n]; zeroes worklist counter.
// ---------------------------------------------------------------------------
__global__ void __launch_bounds__(128) gemm_kernel(const float* __restrict__ x,
                                                   const float* __restrict__ W) {
    if (blockIdx.x == 0 && threadIdx.x == 0) g_wcount = 0;

    __shared__ float ws[COUT * CIN];
    int tid = threadIdx.x;
#pragma unroll
    for (int u = 0; u < 8; u++)
        ((float4*)ws)[tid + u * 128] = ((const float4*)W)[tid + u * 128];
    __syncthreads();

    int b     = blockIdx.x >> 7;
    int ntile = (blockIdx.x & 127) * 64;
    int nl    = tid & 63;
    int o0    = (tid >> 6) * 32;
    int n     = ntile + nl;

    const float* xb = x + b * CIN * NPTS;

    float acc[32];
#pragma unroll
    for (int i = 0; i < 32; i++) acc[i] = 0.0f;

    for (int c = 0; c < CIN; c += 4) {
        float xv0 = xb[(c + 0) * NPTS + n];
        float xv1 = xb[(c + 1) * NPTS + n];
        float xv2 = xb[(c + 2) * NPTS + n];
        float xv3 = xb[(c + 3) * NPTS + n];
#pragma unroll
        for (int i = 0; i < 32; i++) {
            float4 w4 = *(const float4*)&ws[(o0 + i) * CIN + c];
            acc[i] = fmaf(w4.x, xv0, acc[i]);
            acc[i] = fmaf(w4.y, xv1, acc[i]);
            acc[i] = fmaf(w4.z, xv2, acc[i]);
            acc[i] = fmaf(w4.w, xv3, acc[i]);
        }
    }

    float* zp = g_z + ((size_t)b * NPTS + n) * COUT + o0;
#pragma unroll
    for (int i = 0; i < 32; i += 4)
        *(float4*)&zp[i] = make_float4(acc[i], acc[i + 1], acc[i + 2], acc[i + 3]);
}

// ---------------------------------------------------------------------------
// Max-gather + coords passthrough (tail blocks) — measured 16.2us in R5.
// ---------------------------------------------------------------------------
#define MG_BLOCKS   (BB * 256)
#define CP_FLOAT4   (BB * 3 * NPTS / 4)
#define CP_BLOCKS   (CP_FLOAT4 / 256)

__global__ void __launch_bounds__(256) maxgather_kernel(float* __restrict__ y,
                                                        const float* __restrict__ coords) {
    if (blockIdx.x >= MG_BLOCKS) {
        int i = (blockIdx.x - MG_BLOCKS) * 256 + threadIdx.x;
        float4* dst = (float4*)(y + (size_t)BB * COUT * NPTS);
        dst[i] = ((const float4*)coords)[i];
        return;
    }

    __shared__ float yt[COUT][33];

    int tid = threadIdx.x;
    int w   = tid >> 5;
    int l   = tid & 31;
    int b     = blockIdx.x >> 8;
    int ntile = (blockIdx.x & 255) * 32;

    const float* zb = g_z + (size_t)b * NPTS * COUT;
    const float NEG_INF = __int_as_float(0xff800000);

    for (int qq = 0; qq < 4; qq++) {
        int nl = w * 4 + qq;
        int n  = ntile + nl;
        const int* ip = g_idx + ((size_t)b * NPTS + n) * KNN;
        float m0 = NEG_INF, m1 = NEG_INF;
#pragma unroll
        for (int k = 0; k < KNN; k++) {
            int r = __ldg(&ip[k]);
            const float* zr = zb + (size_t)r * COUT;
            m0 = fmaxf(m0, zr[l]);
            m1 = fmaxf(m1, zr[l + 32]);
        }
        yt[l][nl]      = m0;
        yt[l + 32][nl] = m1;
    }
    __syncthreads();

#pragma unroll
    for (int e = tid; e < COUT * 32; e += 256) {
        int o  = e >> 5;
        int nl = e & 31;
        y[((size_t)b * COUT + o) * NPTS + ntile + nl] = yt[o][nl];
    }
}

// ---------------------------------------------------------------------------
extern "C" void kernel_launch(void* const* d_in, const int* in_sizes, int n_in,
                              void* d_out, int out_size) {
    const float* x      = (const float*)d_in[0];
    const float* coords = (const float*)d_in[1];
    const float* W      = (const float*)d_in[2];
    float*       out    = (float*)d_out;

    gemm_kernel<<<BB * 128, 128>>>(x, W);
    knn_thresh<<<NQ / 128, 128>>>(coords);
    knn_collect<<<NQ / 128, 128>>>(coords);
    knn_fallback<<<256, 32>>>(coords);
    maxgather_kernel<<<MG_BLOCKS + CP_BLOCKS, 256>>>(out, coords);
}

// round 9
// speedup vs baseline: 1.8969x; 1.4978x over previous
#include <cuda_runtime.h>

#define BB   4
#define CIN  64
#define COUT 64
#define NPTS 8192
#define KNN  16
#define NQ   (BB * NPTS)
#define CAP  192
#define SAMP 1024
#define TCB  1024   // candidates per collect tile (512 pairs)

// Static scratch (no runtime allocation allowed)
__device__ int   g_idx[NQ * KNN];   // [q][k]      2 MB
__device__ float g_z[NQ * COUT];    // zT[b][n][o] 8 MB
__device__ int   g_wcount;          // fallback worklist size
__device__ int   g_wlist[NQ];       // fallback worklist

// --------------------------- f32x2 helpers ---------------------------------
__device__ __forceinline__ unsigned long long pk2(float lo, float hi) {
    unsigned long long r;
    asm("mov.b64 %0, {%1, %2};" : "=l"(r) : "f"(lo), "f"(hi));
    return r;
}
__device__ __forceinline__ void upk2(unsigned long long v, float& lo, float& hi) {
    asm("mov.b64 {%0, %1}, %2;" : "=f"(lo), "=f"(hi) : "l"(v));
}
__device__ __forceinline__ unsigned long long mul2(unsigned long long a, unsigned long long b) {
    unsigned long long r;
    asm("mul.rn.f32x2 %0, %1, %2;" : "=l"(r) : "l"(a), "l"(b));
    return r;
}
__device__ __forceinline__ unsigned long long add2(unsigned long long a, unsigned long long b) {
    unsigned long long r;
    asm("add.rn.f32x2 %0, %1, %2;" : "=l"(r) : "l"(a), "l"(b));
    return r;
}
__device__ __forceinline__ unsigned long long fma2(unsigned long long a, unsigned long long b,
                                                   unsigned long long c) {
    unsigned long long r;
    asm("fma.rn.f32x2 %0, %1, %2, %3;" : "=l"(r) : "l"(a), "l"(b), "l"(c));
    return r;
}

// ---------------------------------------------------------------------------
// Collect (R5 configuration, verbatim): fused threshold (8th smallest over a
// stride-8 subsample) + full scan with packed f32x2 math; hits d<=T into a
// per-thread local buffer; exact top-16 from the buffer; rare bad queries to
// the fallback worklist.
// ---------------------------------------------------------------------------
__global__ void __launch_bounds__(128) knn_collect(const float* __restrict__ coords) {
    __shared__ float4 stile[TCB];     // phase 1: sample [SAMP]; phase 2: 2 planes of TCB/2

    unsigned long long buf[CAP];      // per-thread local (stack)

    int tid = threadIdx.x;
    int q   = blockIdx.x * 128 + tid;
    int b   = blockIdx.x >> 6;        // 64 blocks per batch
    int n   = q & (NPTS - 1);
    const float* cb = coords + b * 3 * NPTS;

    float qx = cb[n], qy = cb[NPTS + n], qz = cb[2 * NPTS + n];
    float sqi = (qx * qx + qy * qy) + qz * qz;

    // ---- Phase 1: threshold from stride-8 subsample -----------------------
    for (int t = tid; t < SAMP; t += 128) {
        int j = t * 8;
        float cx = cb[j], cy = cb[NPTS + j], cz = cb[2 * NPTS + j];
        stile[t] = make_float4(cx, cy, cz, (cx * cx + cy * cy) + cz * cz);
    }
    __syncthreads();

    float t8[8];
#pragma unroll
    for (int s = 0; s < 8; s++) t8[s] = __int_as_float(0x7f800000);
#pragma unroll 4
    for (int t = 0; t < SAMP; t++) {
        float4 c = stile[t];
        float inner = fmaf(qz, c.z, fmaf(qy, c.y, qx * c.x));
        float d = fmaf(-2.0f, inner, sqi + c.w);
        if (d < t8[7]) {
            float v = d;
#pragma unroll
            for (int s = 0; s < 8; s++) {
                float lo = fminf(t8[s], v);
                float hi = fmaxf(t8[s], v);
                t8[s] = lo; v = hi;
            }
        }
    }
    float T = t8[7];

    // ---- Phase 2: full scan + collect -------------------------------------
    unsigned long long qx2 = pk2(qx, qx), qy2 = pk2(qy, qy), qz2 = pk2(qz, qz);
    unsigned long long sq2 = pk2(sqi, sqi);
    unsigned long long m2  = pk2(-2.0f, -2.0f);

    float4* sxy = stile;              // (x0,x1,y0,y1) per pair  [TCB/2]
    float4* szw = stile + TCB / 2;    // (z0,z1,sq0,sq1) per pair [TCB/2]
    int cnt = 0;

    for (int tb = 0; tb < NPTS; tb += TCB) {
        __syncthreads();
        float* fxy = (float*)sxy;
        float* fzw = (float*)szw;
        for (int e = tid; e < TCB; e += 128) {
            int j = tb + e;
            float cx = cb[j], cy = cb[NPTS + j], cz = cb[2 * NPTS + j];
            int p = e >> 1, o = e & 1;
            fxy[p * 4 + o]     = cx;
            fxy[p * 4 + 2 + o] = cy;
            fzw[p * 4 + o]     = cz;
            fzw[p * 4 + 2 + o] = (cx * cx + cy * cy) + cz * cz;
        }
        __syncthreads();

#pragma unroll 8
        for (int p = 0; p < TCB / 2; p++) {
            float4 a  = sxy[p];
            float4 zz = szw[p];
            unsigned long long x01 = pk2(a.x, a.y),  y01 = pk2(a.z, a.w);
            unsigned long long z01 = pk2(zz.x, zz.y), w01 = pk2(zz.z, zz.w);
            unsigned long long t0 = mul2(qx2, x01);
            t0 = fma2(qy2, y01, t0);
            t0 = fma2(qz2, z01, t0);
            unsigned long long d2 = fma2(m2, t0, add2(sq2, w01));
            float d0, d1;
            upk2(d2, d0, d1);
            if (fminf(d0, d1) <= T) {
                int j0 = tb + 2 * p;
                if (d0 <= T && cnt < CAP) {
                    buf[cnt] = ((unsigned long long)(unsigned)j0 << 32) | __float_as_uint(d0);
                    cnt++;
                }
                if (d1 <= T && cnt < CAP) {
                    buf[cnt] = ((unsigned long long)(unsigned)(j0 + 1) << 32) | __float_as_uint(d1);
                    cnt++;
                }
            }
        }
    }

    // Exact top-16 from buffered candidates (ascending-j order + strict-less
    // insertion reproduces top_k's lowest-index tie-break).
    float ds[KNN];
    int   is_[KNN];
#pragma unroll
    for (int s = 0; s < KNN; s++) { ds[s] = __int_as_float(0x7f800000); is_[s] = 0; }

    for (int t = 0; t < cnt; t++) {
        unsigned long long e = buf[t];
        float d = __uint_as_float((unsigned)e);
        int   j = (int)(e >> 32);
        if (d < ds[KNN - 1]) {
            float vd = d; int vi = j;
#pragma unroll
            for (int s = 0; s < KNN; s++) {
                float od = ds[s]; int oi = is_[s];
                bool  pr = vd < od;
                ds[s]  = pr ? vd : od;
                is_[s] = pr ? vi : oi;
                vd     = pr ? od : vd;
                vi     = pr ? oi : vi;
            }
        }
    }

    int* op = g_idx + q * KNN;
#pragma unroll
    for (int s = 0; s < KNN; s++) op[s] = is_[s];

    if (cnt < KNN || cnt >= CAP) {
        int slot = atomicAdd(&g_wcount, 1);
        g_wlist[slot] = q;
    }
}

// ---------------------------------------------------------------------------
// Fallback: BLOCK-cooperative exact scan (256 threads per flagged query).
// Thread t scans 32 coalesced candidates (unrolled, MLP~24), keeps a private
// sorted top-16 (all slots finite: 32 real candidates each). Per-warp
// lexicographic (d,j) shuffle merge -> 8 sorted 16-lists; warp 0 merges those
// (each lane owns a sorted 4-segment). Exact top_k tie-break throughout.
// ---------------------------------------------------------------------------
__global__ void __launch_bounds__(256) knn_fallback(const float* __restrict__ coords) {
    __shared__ float sd[256][KNN];    // per-thread sorted lists
    __shared__ int   sj[256][KNN];
    __shared__ float md[8 * KNN];     // per-warp merged lists
    __shared__ int   mj[8 * KNN];

    int tid  = threadIdx.x;
    int lane = tid & 31;
    int wid  = tid >> 5;
    int nw   = g_wcount;

    for (int w = blockIdx.x; w < nw; w += 64) {
        int q = g_wlist[w];
        int b = q >> 13, n = q & (NPTS - 1);
        const float* cb = coords + b * 3 * NPTS;
        float qx = cb[n], qy = cb[NPTS + n], qz = cb[2 * NPTS + n];
        float sqi = (qx * qx + qy * qy) + qz * qz;

        // ---- per-thread scan: 32 candidates, ascending j ------------------
        float ds[KNN];
        int   is_[KNN];
#pragma unroll
        for (int s = 0; s < KNN; s++) { ds[s] = __int_as_float(0x7f800000); is_[s] = 0x7fffffff; }

        for (int i0 = 0; i0 < 32; i0 += 8) {
            float cxs[8], cys[8], czs[8];
#pragma unroll
            for (int u = 0; u < 8; u++) {
                int j = (i0 + u) * 256 + tid;
                cxs[u] = __ldg(cb + j);
                cys[u] = __ldg(cb + NPTS + j);
                czs[u] = __ldg(cb + 2 * NPTS + j);
            }
#pragma unroll
            for (int u = 0; u < 8; u++) {
                int j = (i0 + u) * 256 + tid;
                float sq = (cxs[u] * cxs[u] + cys[u] * cys[u]) + czs[u] * czs[u];
                float inner = fmaf(qz, czs[u], fmaf(qy, cys[u], qx * cxs[u]));
                float d = fmaf(-2.0f, inner, sqi + sq);
                if (d < ds[KNN - 1]) {
                    float vd = d; int vi = j;
#pragma unroll
                    for (int s = 0; s < KNN; s++) {
                        float od = ds[s]; int oi = is_[s];
                        bool  pr = vd < od;
                        ds[s]  = pr ? vd : od;
                        is_[s] = pr ? vi : oi;
                        vd     = pr ? od : vd;
                        vi     = pr ? oi : vi;
                    }
                }
            }
        }

#pragma unroll
        for (int s = 0; s < KNN; s++) { sd[tid][s] = ds[s]; sj[tid][s] = is_[s]; }
        __syncthreads();

        // ---- per-warp merge: 32 sorted 16-lists -> sorted 16-list ---------
        {
            int ptr = 0;
            for (int k = 0; k < KNN; k++) {
                float cd = (ptr < KNN) ? sd[tid][ptr] : __int_as_float(0x7f800000);
                int   cj = (ptr < KNN) ? sj[tid][ptr] : 0x7fffffff;
                float wd = cd; int wj = cj;
#pragma unroll
                for (int off = 16; off > 0; off >>= 1) {
                    float od = __shfl_xor_sync(0xffffffffu, wd, off);
                    int   oj = __shfl_xor_sync(0xffffffffu, wj, off);
                    if (od < wd || (od == wd && oj < wj)) { wd = od; wj = oj; }
                }
                if (wd == cd && wj == cj) ptr++;   // j unique -> one lane advances
                if (lane == 0) { md[wid * KNN + k] = wd; mj[wid * KNN + k] = wj; }
            }
        }
        __syncthreads();

        // ---- final merge by warp 0: 8 sorted 16-lists (lane = 4-segment) --
        if (wid == 0) {
            float fd[4]; int fj[4];
            int base = (lane >> 2) * KNN + (lane & 3) * 4;
#pragma unroll
            for (int t = 0; t < 4; t++) { fd[t] = md[base + t]; fj[t] = mj[base + t]; }
            int ptr = 0;
            for (int k = 0; k < KNN; k++) {
                float cd = (ptr < 4) ? fd[ptr] : __int_as_float(0x7f800000);
                int   cj = (ptr < 4) ? fj[ptr] : 0x7fffffff;
                float wd = cd; int wj = cj;
#pragma unroll
                for (int off = 16; off > 0; off >>= 1) {
                    float od = __shfl_xor_sync(0xffffffffu, wd, off);
                    int   oj = __shfl_xor_sync(0xffffffffu, wj, off);
                    if (od < wd || (od == wd && oj < wj)) { wd = od; wj = oj; }
                }
                if (wd == cd && wj == cj) ptr++;
                if (lane == 0) g_idx[q * KNN + k] = wj;
            }
        }
        __syncthreads();   // smem reused next worklist entry
    }
}

// ---------------------------------------------------------------------------
// GEMM: z[b][n][o] = sum_c W[o][c] * x[b][c][n]; zeroes worklist counter.
// ---------------------------------------------------------------------------
__global__ void __launch_bounds__(128) gemm_kernel(const float* __restrict__ x,
                                                   const float* __restrict__ W) {
    if (blockIdx.x == 0 && threadIdx.x == 0) g_wcount = 0;

    __shared__ float ws[COUT * CIN];
    int tid = threadIdx.x;
#pragma unroll
    for (int u = 0; u < 8; u++)
        ((float4*)ws)[tid + u * 128] = ((const float4*)W)[tid + u * 128];
    __syncthreads();

    int b     = blockIdx.x >> 7;          // 128 n-tiles of 64 per batch
    int ntile = (blockIdx.x & 127) * 64;
    int nl    = tid & 63;
    int o0    = (tid >> 6) * 32;
    int n     = ntile + nl;

    const float* xb = x + b * CIN * NPTS;

    float acc[32];
#pragma unroll
    for (int i = 0; i < 32; i++) acc[i] = 0.0f;

    for (int c = 0; c < CIN; c += 4) {
        float xv0 = xb[(c + 0) * NPTS + n];
        float xv1 = xb[(c + 1) * NPTS + n];
        float xv2 = xb[(c + 2) * NPTS + n];
        float xv3 = xb[(c + 3) * NPTS + n];
#pragma unroll
        for (int i = 0; i < 32; i++) {
            float4 w4 = *(const float4*)&ws[(o0 + i) * CIN + c];
            acc[i] = fmaf(w4.x, xv0, acc[i]);
            acc[i] = fmaf(w4.y, xv1, acc[i]);
            acc[i] = fmaf(w4.z, xv2, acc[i]);
            acc[i] = fmaf(w4.w, xv3, acc[i]);
        }
    }

    float* zp = g_z + ((size_t)b * NPTS + n) * COUT + o0;
#pragma unroll
    for (int i = 0; i < 32; i += 4)
        *(float4*)&zp[i] = make_float4(acc[i], acc[i + 1], acc[i + 2], acc[i + 3]);
}

// ---------------------------------------------------------------------------
// Max-gather + coords passthrough (tail blocks).
// ---------------------------------------------------------------------------
#define MG_BLOCKS   (BB * 256)
#define CP_FLOAT4   (BB * 3 * NPTS / 4)
#define CP_BLOCKS   (CP_FLOAT4 / 256)

__global__ void __launch_bounds__(256) maxgather_kernel(float* __restrict__ y,
                                                        const float* __restrict__ coords) {
    if (blockIdx.x >= MG_BLOCKS) {
        int i = (blockIdx.x - MG_BLOCKS) * 256 + threadIdx.x;
        float4* dst = (float4*)(y + (size_t)BB * COUT * NPTS);
        dst[i] = ((const float4*)coords)[i];
        return;
    }

    __shared__ float yt[COUT][33];

    int tid = threadIdx.x;
    int w   = tid >> 5;
    int l   = tid & 31;
    int b     = blockIdx.x >> 8;
    int ntile = (blockIdx.x & 255) * 32;

    const float* zb = g_z + (size_t)b * NPTS * COUT;
    const float NEG_INF = __int_as_float(0xff800000);

    for (int qq = 0; qq < 4; qq++) {
        int nl = w * 4 + qq;
        int n  = ntile + nl;
        const int* ip = g_idx + ((size_t)b * NPTS + n) * KNN;
        float m0 = NEG_INF, m1 = NEG_INF;
#pragma unroll
        for (int k = 0; k < KNN; k++) {
            int r = __ldg(&ip[k]);
            const float* zr = zb + (size_t)r * COUT;
            m0 = fmaxf(m0, zr[l]);
            m1 = fmaxf(m1, zr[l + 32]);
        }
        yt[l][nl]      = m0;
        yt[l + 32][nl] = m1;
    }
    __syncthreads();

#pragma unroll
    for (int e = tid; e < COUT * 32; e += 256) {
        int o  = e >> 5;
        int nl = e & 31;
        y[((size_t)b * COUT + o) * NPTS + ntile + nl] = yt[o][nl];
    }
}

// ---------------------------------------------------------------------------
extern "C" void kernel_launch(void* const* d_in, const int* in_sizes, int n_in,
                              void* d_out, int out_size) {
    const float* x      = (const float*)d_in[0];
    const float* coords = (const float*)d_in[1];
    const float* W      = (const float*)d_in[2];
    float*       out    = (float*)d_out;

    gemm_kernel<<<BB * 128, 128>>>(x, W);
    knn_collect<<<NQ / 128, 128>>>(coords);
    knn_fallback<<<64, 256>>>(coords);
    maxgather_kernel<<<MG_BLOCKS + CP_BLOCKS, 256>>>(out, coords);
}

// round 11
// speedup vs baseline: 2.0041x; 1.0565x over previous
#include <cuda_runtime.h>

#define BB   4
#define CIN  64
#define COUT 64
#define NPTS 8192
#define KNN  16
#define NQ   (BB * NPTS)
#define CAPH 128            // per-thread (per-half) hit buffer
#define SAMP 1024
#define HALFC 4096          // candidates per half-thread

// Static scratch (no runtime allocation allowed)
__device__ int   g_idx[NQ * KNN];   // [q][k]      2 MB
__device__ float g_z[NQ * COUT];    // zT[b][n][o] 8 MB
__device__ int   g_wcount;          // fallback worklist size
__device__ int   g_wlist[NQ];       // fallback worklist

// --------------------------- f32x2 helpers ---------------------------------
__device__ __forceinline__ unsigned long long pk2(float lo, float hi) {
    unsigned long long r;
    asm("mov.b64 %0, {%1, %2};" : "=l"(r) : "f"(lo), "f"(hi));
    return r;
}
__device__ __forceinline__ void upk2(unsigned long long v, float& lo, float& hi) {
    asm("mov.b64 {%0, %1}, %2;" : "=f"(lo), "=f"(hi) : "l"(v));
}
__device__ __forceinline__ unsigned long long mul2(unsigned long long a, unsigned long long b) {
    unsigned long long r;
    asm("mul.rn.f32x2 %0, %1, %2;" : "=l"(r) : "l"(a), "l"(b));
    return r;
}
__device__ __forceinline__ unsigned long long add2(unsigned long long a, unsigned long long b) {
    unsigned long long r;
    asm("add.rn.f32x2 %0, %1, %2;" : "=l"(r) : "l"(a), "l"(b));
    return r;
}
__device__ __forceinline__ unsigned long long fma2(unsigned long long a, unsigned long long b,
                                                   unsigned long long c) {
    unsigned long long r;
    asm("fma.rn.f32x2 %0, %1, %2, %3;" : "=l"(r) : "l"(a), "l"(b), "l"(c));
    return r;
}

// ---------------------------------------------------------------------------
// Collect, 2-way candidate split: 256 threads per block, 128 queries per
// block. Threads t and t+128 share query q=block*128+t; each scans one half
// (4096 candidates) via smem tiles, collecting hits d<=T (T = 8th smallest
// over a stride-8 subsample, computed redundantly by both) into a local
// buffer, then selects a sorted top-16. Thread t<128 merges partner's list
// (exact, stable tie-break) and writes g_idx. Rare bad queries -> worklist.
// ---------------------------------------------------------------------------
__global__ void __launch_bounds__(256) knn_collect(const float* __restrict__ coords) {
    // Tile staging: 2 regions x 512 pairs x 8 floats (x0,x1,y0,y1,z0,z1,w0,w1)
    // = 32KB. Reused afterward for the 256 sorted 16-lists (32KB).
    __shared__ __align__(16) float st[2][4096];
    __shared__ int scnt[256];

    unsigned long long buf[CAPH];     // per-thread local (stack)

    int tid = threadIdx.x;            // 0..255
    int ql  = tid & 127;              // query lane
    int h   = tid >> 7;               // half: 0 or 1
    int q   = blockIdx.x * 128 + ql;
    int b   = blockIdx.x >> 6;        // 64 blocks per batch
    int n   = q & (NPTS - 1);
    const float* cb = coords + b * 3 * NPTS;

    float qx = cb[n], qy = cb[NPTS + n], qz = cb[2 * NPTS + n];
    float sqi = (qx * qx + qy * qy) + qz * qz;

    // ---- Phase 1: threshold from stride-8 subsample (redundant per pair) --
    float T;
    {
        float4* sp = (float4*)&st[0][0];   // 1024 float4 = 16KB
        for (int t = tid; t < SAMP; t += 256) {
            int j = t * 8;
            float cx = cb[j], cy = cb[NPTS + j], cz = cb[2 * NPTS + j];
            sp[t] = make_float4(cx, cy, cz, (cx * cx + cy * cy) + cz * cz);
        }
        __syncthreads();

        float t8[8];
#pragma unroll
        for (int s = 0; s < 8; s++) t8[s] = __int_as_float(0x7f800000);
#pragma unroll 4
        for (int t = 0; t < SAMP; t++) {
            float4 c = sp[t];
            float inner = fmaf(qz, c.z, fmaf(qy, c.y, qx * c.x));
            float d = fmaf(-2.0f, inner, sqi + c.w);
            if (d < t8[7]) {
                float v = d;
#pragma unroll
                for (int s = 0; s < 8; s++) {
                    float lo = fminf(t8[s], v);
                    float hi = fmaxf(t8[s], v);
                    t8[s] = lo; v = hi;
                }
            }
        }
        T = t8[7];
    }

    // ---- Phase 2: half-scan + collect -------------------------------------
    unsigned long long qx2 = pk2(qx, qx), qy2 = pk2(qy, qy), qz2 = pk2(qz, qz);
    unsigned long long sq2 = pk2(sqi, sqi);
    unsigned long long m2  = pk2(-2.0f, -2.0f);

    int cnt = 0;
    for (int step = 0; step < 4; step++) {
        __syncthreads();               // prior readers done (incl. phase-1 sample)
        // Stage one 1024-candidate tile per region.
        for (int e = tid; e < 2048; e += 256) {
            int r  = e >> 10;
            int ei = e & 1023;
            int j  = r * HALFC + step * 1024 + ei;
            float cx = cb[j], cy = cb[NPTS + j], cz = cb[2 * NPTS + j];
            float* f = st[r];
            int p = ei >> 1, o = ei & 1;
            f[p * 8 + o]     = cx;
            f[p * 8 + 2 + o] = cy;
            f[p * 8 + 4 + o] = cz;
            f[p * 8 + 6 + o] = (cx * cx + cy * cy) + cz * cz;
        }
        __syncthreads();

        const float* f = st[h];
        int jbase = h * HALFC + step * 1024;
#pragma unroll 8
        for (int p = 0; p < 512; p++) {
            ulonglong2 a = *(const ulonglong2*)(f + p * 8);      // x01, y01
            ulonglong2 c = *(const ulonglong2*)(f + p * 8 + 4);  // z01, w01
            unsigned long long t0 = mul2(qx2, a.x);
            t0 = fma2(qy2, a.y, t0);
            t0 = fma2(qz2, c.x, t0);
            unsigned long long d2 = fma2(m2, t0, add2(sq2, c.y));
            float d0, d1;
            upk2(d2, d0, d1);
            if (fminf(d0, d1) <= T) {
                int j0 = jbase + 2 * p;
                if (d0 <= T) {
                    if (cnt < CAPH)
                        buf[cnt] = ((unsigned long long)(unsigned)j0 << 32) | __float_as_uint(d0);
                    cnt++;
                }
                if (d1 <= T) {
                    if (cnt < CAPH)
                        buf[cnt] = ((unsigned long long)(unsigned)(j0 + 1) << 32) | __float_as_uint(d1);
                    cnt++;
                }
            }
        }
    }

    // ---- per-thread sorted top-16 from buffer -----------------------------
    float ds[KNN];
    int   is_[KNN];
#pragma unroll
    for (int s = 0; s < KNN; s++) { ds[s] = __int_as_float(0x7f800000); is_[s] = 0; }

    int m = cnt < CAPH ? cnt : CAPH;
    for (int t = 0; t < m; t++) {
        unsigned long long e = buf[t];
        float d = __uint_as_float((unsigned)e);
        int   j = (int)(e >> 32);
        if (d < ds[KNN - 1]) {
            float vd = d; int vi = j;
#pragma unroll
            for (int s = 0; s < KNN; s++) {
                float od = ds[s]; int oi = is_[s];
                bool  pr = vd < od;
                ds[s]  = pr ? vd : od;
                is_[s] = pr ? vi : oi;
                vd     = pr ? od : vd;
                vi     = pr ? oi : vi;
            }
        }
    }

    // ---- publish lists + counts, then merge (half 0 owns the query) -------
    __syncthreads();                   // done reading tiles; reuse st for lists
    float* Ld = (float*)&st[0][0];             // [256][16] floats, 16KB
    int*   Lj = (int*)&st[0][0] + 256 * KNN;   // [256][16] ints,   16KB
#pragma unroll
    for (int s = 0; s < KNN; s++) { Ld[tid * KNN + s] = ds[s]; Lj[tid * KNN + s] = is_[s]; }
    scnt[tid] = cnt;
    __syncthreads();

    if (h == 0) {
        int cntB = scnt[tid + 128];
        // Insert partner's sorted 16-list (half-1: all j >= HALFC > any half-0
        // j, list ascending (d, j)) into ours with strict-less bubble —
        // reproduces top_k's lowest-index tie-break exactly.
#pragma unroll
        for (int s2 = 0; s2 < KNN; s2++) {
            float d = Ld[(tid + 128) * KNN + s2];
            int   j = Lj[(tid + 128) * KNN + s2];
            if (d < ds[KNN - 1]) {
                float vd = d; int vi = j;
#pragma unroll
                for (int s = 0; s < KNN; s++) {
                    float od = ds[s]; int oi = is_[s];
                    bool  pr = vd < od;
                    ds[s]  = pr ? vd : od;
                    is_[s] = pr ? vi : oi;
                    vd     = pr ? od : vd;
                    vi     = pr ? oi : vi;
                }
            }
        }

        int* op = g_idx + q * KNN;
#pragma unroll
        for (int s = 0; s < KNN; s++) op[s] = is_[s];

        if (cnt + cntB < KNN || cnt > CAPH || cntB > CAPH) {
            int slot = atomicAdd(&g_wcount, 1);
            g_wlist[slot] = q;
        }
    }
}

// ---------------------------------------------------------------------------
// Fallback: BLOCK-cooperative exact scan (256 threads per flagged query) —
// unchanged from R9 (verified).
// ---------------------------------------------------------------------------
__global__ void __launch_bounds__(256) knn_fallback(const float* __restrict__ coords) {
    __shared__ float sd[256][KNN];
    __shared__ int   sj[256][KNN];
    __shared__ float md[8 * KNN];
    __shared__ int   mj[8 * KNN];

    int tid  = threadIdx.x;
    int lane = tid & 31;
    int wid  = tid >> 5;
    int nw   = g_wcount;

    for (int w = blockIdx.x; w < nw; w += 64) {
        int q = g_wlist[w];
        int b = q >> 13, n = q & (NPTS - 1);
        const float* cb = coords + b * 3 * NPTS;
        float qx = cb[n], qy = cb[NPTS + n], qz = cb[2 * NPTS + n];
        float sqi = (qx * qx + qy * qy) + qz * qz;

        float ds[KNN];
        int   is_[KNN];
#pragma unroll
        for (int s = 0; s < KNN; s++) { ds[s] = __int_as_float(0x7f800000); is_[s] = 0x7fffffff; }

        for (int i0 = 0; i0 < 32; i0 += 8) {
            float cxs[8], cys[8], czs[8];
#pragma unroll
            for (int u = 0; u < 8; u++) {
                int j = (i0 + u) * 256 + tid;
                cxs[u] = __ldg(cb + j);
                cys[u] = __ldg(cb + NPTS + j);
                czs[u] = __ldg(cb + 2 * NPTS + j);
            }
#pragma unroll
            for (int u = 0; u < 8; u++) {
                int j = (i0 + u) * 256 + tid;
                float sq = (cxs[u] * cxs[u] + cys[u] * cys[u]) + czs[u] * czs[u];
                float inner = fmaf(qz, czs[u], fmaf(qy, cys[u], qx * cxs[u]));
                float d = fmaf(-2.0f, inner, sqi + sq);
                if (d < ds[KNN - 1]) {
                    float vd = d; int vi = j;
#pragma unroll
                    for (int s = 0; s < KNN; s++) {
                        float od = ds[s]; int oi = is_[s];
                        bool  pr = vd < od;
                        ds[s]  = pr ? vd : od;
                        is_[s] = pr ? vi : oi;
                        vd     = pr ? od : vd;
                        vi     = pr ? oi : vi;
                    }
                }
            }
        }

#pragma unroll
        for (int s = 0; s < KNN; s++) { sd[tid][s] = ds[s]; sj[tid][s] = is_[s]; }
        __syncthreads();

        {
            int ptr = 0;
            for (int k = 0; k < KNN; k++) {
                float cd = (ptr < KNN) ? sd[tid][ptr] : __int_as_float(0x7f800000);
                int   cj = (ptr < KNN) ? sj[tid][ptr] : 0x7fffffff;
                float wd = cd; int wj = cj;
#pragma unroll
                for (int off = 16; off > 0; off >>= 1) {
                    float od = __shfl_xor_sync(0xffffffffu, wd, off);
                    int   oj = __shfl_xor_sync(0xffffffffu, wj, off);
                    if (od < wd || (od == wd && oj < wj)) { wd = od; wj = oj; }
                }
                if (wd == cd && wj == cj) ptr++;
                if (lane == 0) { md[wid * KNN + k] = wd; mj[wid * KNN + k] = wj; }
            }
        }
        __syncthreads();

        if (wid == 0) {
            float fd[4]; int fj[4];
            int base = (lane >> 2) * KNN + (lane & 3) * 4;
#pragma unroll
            for (int t = 0; t < 4; t++) { fd[t] = md[base + t]; fj[t] = mj[base + t]; }
            int ptr = 0;
            for (int k = 0; k < KNN; k++) {
                float cd = (ptr < 4) ? fd[ptr] : __int_as_float(0x7f800000);
                int   cj = (ptr < 4) ? fj[ptr] : 0x7fffffff;
                float wd = cd; int wj = cj;
#pragma unroll
                for (int off = 16; off > 0; off >>= 1) {
                    float od = __shfl_xor_sync(0xffffffffu, wd, off);
                    int   oj = __shfl_xor_sync(0xffffffffu, wj, off);
                    if (od < wd || (od == wd && oj < wj)) { wd = od; wj = oj; }
                }
                if (wd == cd && wj == cj) ptr++;
                if (lane == 0) g_idx[q * KNN + k] = wj;
            }
        }
        __syncthreads();
    }
}

// ---------------------------------------------------------------------------
// GEMM: z[b][n][o] = sum_c W[o][c] * x[b][c][n]; zeroes worklist counter.
// ---------------------------------------------------------------------------
__global__ void __launch_bounds__(128) gemm_kernel(const float* __restrict__ x,
                                                   const float* __restrict__ W) {
    if (blockIdx.x == 0 && threadIdx.x == 0) g_wcount = 0;

    __shared__ float ws[COUT * CIN];
    int tid = threadIdx.x;
#pragma unroll
    for (int u = 0; u < 8; u++)
        ((float4*)ws)[tid + u * 128] = ((const float4*)W)[tid + u * 128];
    __syncthreads();

    int b     = blockIdx.x >> 7;
    int ntile = (blockIdx.x & 127) * 64;
    int nl    = tid & 63;
    int o0    = (tid >> 6) * 32;
    int n     = ntile + nl;

    const float* xb = x + b * CIN * NPTS;

    float acc[32];
#pragma unroll
    for (int i = 0; i < 32; i++) acc[i] = 0.0f;

    for (int c = 0; c < CIN; c += 4) {
        float xv0 = xb[(c + 0) * NPTS + n];
        float xv1 = xb[(c + 1) * NPTS + n];
        float xv2 = xb[(c + 2) * NPTS + n];
        float xv3 = xb[(c + 3) * NPTS + n];
#pragma unroll
        for (int i = 0; i < 32; i++) {
            float4 w4 = *(const float4*)&ws[(o0 + i) * CIN + c];
            acc[i] = fmaf(w4.x, xv0, acc[i]);
            acc[i] = fmaf(w4.y, xv1, acc[i]);
            acc[i] = fmaf(w4.z, xv2, acc[i]);
            acc[i] = fmaf(w4.w, xv3, acc[i]);
        }
    }

    float* zp = g_z + ((size_t)b * NPTS + n) * COUT + o0;
#pragma unroll
    for (int i = 0; i < 32; i += 4)
        *(float4*)&zp[i] = make_float4(acc[i], acc[i + 1], acc[i + 2], acc[i + 3]);
}

// ---------------------------------------------------------------------------
// Max-gather + coords passthrough (tail blocks).
// ---------------------------------------------------------------------------
#define MG_BLOCKS   (BB * 256)
#define CP_FLOAT4   (BB * 3 * NPTS / 4)
#define CP_BLOCKS   (CP_FLOAT4 / 256)

__global__ void __launch_bounds__(256) maxgather_kernel(float* __restrict__ y,
                                                        const float* __restrict__ coords) {
    if (blockIdx.x >= MG_BLOCKS) {
        int i = (blockIdx.x - MG_BLOCKS) * 256 + threadIdx.x;
        float4* dst = (float4*)(y + (size_t)BB * COUT * NPTS);
        dst[i] = ((const float4*)coords)[i];
        return;
    }

    __shared__ float yt[COUT][33];

    int tid = threadIdx.x;
    int w   = tid >> 5;
    int l   = tid & 31;
    int b     = blockIdx.x >> 8;
    int ntile = (blockIdx.x & 255) * 32;

    const float* zb = g_z + (size_t)b * NPTS * COUT;
    const float NEG_INF = __int_as_float(0xff800000);

    for (int qq = 0; qq < 4; qq++) {
        int nl = w * 4 + qq;
        int n  = ntile + nl;
        const int* ip = g_idx + ((size_t)b * NPTS + n) * KNN;
        float m0 = NEG_INF, m1 = NEG_INF;
#pragma unroll
        for (int k = 0; k < KNN; k++) {
            int r = __ldg(&ip[k]);
            const float* zr = zb + (size_t)r * COUT;
            m0 = fmaxf(m0, zr[l]);
            m1 = fmaxf(m1, zr[l + 32]);
        }
        yt[l][nl]      = m0;
        yt[l + 32][nl] = m1;
    }
    __syncthreads();

#pragma unroll
    for (int e = tid; e < COUT * 32; e += 256) {
        int o  = e >> 5;
        int nl = e & 31;
        y[((size_t)b * COUT + o) * NPTS + ntile + nl] = yt[o][nl];
    }
}

// ---------------------------------------------------------------------------
extern "C" void kernel_launch(void* const* d_in, const int* in_sizes, int n_in,
                              void* d_out, int out_size) {
    const float* x      = (const float*)d_in[0];
    const float* coords = (const float*)d_in[1];
    const float* W      = (const float*)d_in[2];
    float*       out    = (float*)d_out;

    gemm_kernel<<<BB * 128, 128>>>(x, W);
    knn_collect<<<NQ / 128, 256>>>(coords);
    knn_fallback<<<64, 256>>>(coords);
    maxgather_kernel<<<MG_BLOCKS + CP_BLOCKS, 256>>>(out, coords);
}

// round 12
// speedup vs baseline: 2.5151x; 1.2550x over previous
#include <cuda_runtime.h>

#define BB   4
#define CIN  64
#define COUT 64
#define NPTS 8192
#define KNN  16
#define NQ   (BB * NPTS)
#define QPB  64             // queries per collect block
#define CAPQ 48             // per-thread (per-quarter) hit buffer
#define QCAND 2048          // candidates per quarter-thread
#define STEPC 512           // candidates per region per step

// Static scratch (no runtime allocation allowed)
__device__ int   g_idx[NQ * KNN];   // [q][k]      2 MB
__device__ float g_z[NQ * COUT];    // zT[b][n][o] 8 MB
__device__ int   g_wcount;          // fallback worklist size
__device__ int   g_wlist[NQ];       // fallback worklist

// --------------------------- f32x2 helpers ---------------------------------
__device__ __forceinline__ unsigned long long pk2(float lo, float hi) {
    unsigned long long r;
    asm("mov.b64 %0, {%1, %2};" : "=l"(r) : "f"(lo), "f"(hi));
    return r;
}
__device__ __forceinline__ void upk2(unsigned long long v, float& lo, float& hi) {
    asm("mov.b64 {%0, %1}, %2;" : "=f"(lo), "=f"(hi) : "l"(v));
}
__device__ __forceinline__ unsigned long long mul2(unsigned long long a, unsigned long long b) {
    unsigned long long r;
    asm("mul.rn.f32x2 %0, %1, %2;" : "=l"(r) : "l"(a), "l"(b));
    return r;
}
__device__ __forceinline__ unsigned long long add2(unsigned long long a, unsigned long long b) {
    unsigned long long r;
    asm("add.rn.f32x2 %0, %1, %2;" : "=l"(r) : "l"(a), "l"(b));
    return r;
}
__device__ __forceinline__ unsigned long long fma2(unsigned long long a, unsigned long long b,
                                                   unsigned long long c) {
    unsigned long long r;
    asm("fma.rn.f32x2 %0, %1, %2, %3;" : "=l"(r) : "l"(a), "l"(b), "l"(c));
    return r;
}

// ---------------------------------------------------------------------------
// Collect, 4-way candidate split: 256 threads, 64 queries per block (512
// blocks -> 3.46 blocks/SM). Threads (ql, ql+64, ql+128, ql+192) share query
// q = block*64+ql; quarter h scans candidates [h*2048, (h+1)*2048) via smem
// tiles. Threshold T (8th smallest of a 1024-point stride-8 subsample) is
// computed cooperatively: each quarter scans 256 samples keeping top-8, the
// four sorted 8-lists are merged per-thread (value selection — order-
// independent, so all partners get the identical T). Hits d<=T go to a
// 48-entry local buffer -> per-thread sorted top-16 -> owner (h==0) merges
// partners' lists in quarter order (exact top_k tie-break). Rare bad queries
// -> fallback worklist.
// ---------------------------------------------------------------------------
__global__ void __launch_bounds__(256) knn_collect(const float* __restrict__ coords) {
    // 32KB staging: phase 1 = 1024 sample float4 (16KB) + four top-8 lists
    // (8KB); phase 2 = 4 regions x 256 pairs x 8 floats; end = 256 16-lists.
    __shared__ __align__(16) float st[4][2048];
    __shared__ int scnt[256];

    unsigned long long buf[CAPQ];     // per-thread local (stack)

    int tid = threadIdx.x;            // 0..255
    int ql  = tid & 63;               // query lane
    int h   = tid >> 6;               // quarter: 0..3
    int q   = blockIdx.x * QPB + ql;
    int b   = blockIdx.x >> 7;        // 128 blocks per batch
    int n   = q & (NPTS - 1);
    const float* cb = coords + b * 3 * NPTS;

    float qx = cb[n], qy = cb[NPTS + n], qz = cb[2 * NPTS + n];
    float sqi = (qx * qx + qy * qy) + qz * qz;

    // ---- Phase 1: cooperative threshold -----------------------------------
    float T;
    {
        float4* sp = (float4*)&st[0][0];   // 1024 float4 = 16KB (st[0..1])
        for (int t = tid; t < 1024; t += 256) {
            int j = t * 8;
            float cx = cb[j], cy = cb[NPTS + j], cz = cb[2 * NPTS + j];
            sp[t] = make_float4(cx, cy, cz, (cx * cx + cy * cy) + cz * cz);
        }
        __syncthreads();

        float t8[8];
#pragma unroll
        for (int s = 0; s < 8; s++) t8[s] = __int_as_float(0x7f800000);
#pragma unroll 4
        for (int tt = 0; tt < 256; tt++) {
            float4 c = sp[h * 256 + tt];
            float inner = fmaf(qz, c.z, fmaf(qy, c.y, qx * c.x));
            float d = fmaf(-2.0f, inner, sqi + c.w);
            if (d < t8[7]) {
                float v = d;
#pragma unroll
                for (int s = 0; s < 8; s++) {
                    float lo = fminf(t8[s], v);
                    float hi = fmaxf(t8[s], v);
                    t8[s] = lo; v = hi;
                }
            }
        }

        // Publish the four sorted 8-lists (8KB, in st[2]) and merge values.
        float* L8 = &st[2][0];
#pragma unroll
        for (int s = 0; s < 8; s++) L8[tid * 8 + s] = t8[s];
        __syncthreads();

#pragma unroll
        for (int k = 1; k < 4; k++) {
            int pt = ql + (((h + k) & 3) << 6);
#pragma unroll
            for (int s = 0; s < 8; s++) {
                float v = L8[pt * 8 + s];
                if (v < t8[7]) {
                    float w = v;
#pragma unroll
                    for (int s2 = 0; s2 < 8; s2++) {
                        float lo = fminf(t8[s2], w);
                        float hi = fmaxf(t8[s2], w);
                        t8[s2] = lo; w = hi;
                    }
                }
            }
        }
        T = t8[7];    // 8th smallest value of the 1024-sample union
    }

    // ---- Phase 2: quarter-scan + collect ----------------------------------
    unsigned long long qx2 = pk2(qx, qx), qy2 = pk2(qy, qy), qz2 = pk2(qz, qz);
    unsigned long long sq2 = pk2(sqi, sqi);
    unsigned long long m2  = pk2(-2.0f, -2.0f);

    int cnt = 0;
    for (int step = 0; step < 4; step++) {
        __syncthreads();               // prior readers done
        // Stage: region r holds quarter r's current 512-candidate window.
        for (int e = tid; e < 2048; e += 256) {
            int r  = e >> 9;
            int ei = e & 511;
            int j  = r * QCAND + step * STEPC + ei;
            float cx = cb[j], cy = cb[NPTS + j], cz = cb[2 * NPTS + j];
            float* f = st[r];
            int p = ei >> 1, o = ei & 1;
            f[p * 8 + o]     = cx;
            f[p * 8 + 2 + o] = cy;
            f[p * 8 + 4 + o] = cz;
            f[p * 8 + 6 + o] = (cx * cx + cy * cy) + cz * cz;
        }
        __syncthreads();

        const float* f = st[h];
        int jbase = h * QCAND + step * STEPC;
#pragma unroll 8
        for (int p = 0; p < 256; p++) {
            ulonglong2 a = *(const ulonglong2*)(f + p * 8);      // x01, y01
            ulonglong2 c = *(const ulonglong2*)(f + p * 8 + 4);  // z01, w01
            unsigned long long t0 = mul2(qx2, a.x);
            t0 = fma2(qy2, a.y, t0);
            t0 = fma2(qz2, c.x, t0);
            unsigned long long d2 = fma2(m2, t0, add2(sq2, c.y));
            float d0, d1;
            upk2(d2, d0, d1);
            if (fminf(d0, d1) <= T) {
                int j0 = jbase + 2 * p;
                if (d0 <= T) {
                    if (cnt < CAPQ)
                        buf[cnt] = ((unsigned long long)(unsigned)j0 << 32) | __float_as_uint(d0);
                    cnt++;
                }
                if (d1 <= T) {
                    if (cnt < CAPQ)
                        buf[cnt] = ((unsigned long long)(unsigned)(j0 + 1) << 32) | __float_as_uint(d1);
                    cnt++;
                }
            }
        }
    }

    // ---- per-thread sorted top-16 from buffer -----------------------------
    float ds[KNN];
    int   is_[KNN];
#pragma unroll
    for (int s = 0; s < KNN; s++) { ds[s] = __int_as_float(0x7f800000); is_[s] = 0; }

    int m = cnt < CAPQ ? cnt : CAPQ;
    for (int t = 0; t < m; t++) {
        unsigned long long e = buf[t];
        float d = __uint_as_float((unsigned)e);
        int   j = (int)(e >> 32);
        if (d < ds[KNN - 1]) {
            float vd = d; int vi = j;
#pragma unroll
            for (int s = 0; s < KNN; s++) {
                float od = ds[s]; int oi = is_[s];
                bool  pr = vd < od;
                ds[s]  = pr ? vd : od;
                is_[s] = pr ? vi : oi;
                vd     = pr ? od : vd;
                vi     = pr ? oi : vi;
            }
        }
    }

    // ---- publish lists + counts, merge (quarter 0 owns the query) ---------
    __syncthreads();                   // done reading tiles; reuse st
    float* Ld = (float*)&st[0][0];             // [256][16] floats, 16KB
    int*   Lj = (int*)&st[0][0] + 256 * KNN;   // [256][16] ints,   16KB
#pragma unroll
    for (int s = 0; s < KNN; s++) { Ld[tid * KNN + s] = ds[s]; Lj[tid * KNN + s] = is_[s]; }
    scnt[tid] = cnt;
    __syncthreads();

    if (h == 0) {
        int bad = (cnt > CAPQ);
        int total = cnt;
        // Insert partners in quarter order 1,2,3 (their j ranges ascend), so
        // the strict-less bubble reproduces top_k's lowest-index tie-break.
#pragma unroll
        for (int k = 1; k < 4; k++) {
            int pt = ql + (k << 6);
            int ck = scnt[pt];
            total += ck;
            bad |= (ck > CAPQ);
#pragma unroll
            for (int s2 = 0; s2 < KNN; s2++) {
                float d = Ld[pt * KNN + s2];
                int   j = Lj[pt * KNN + s2];
                if (d < ds[KNN - 1]) {
                    float vd = d; int vi = j;
#pragma unroll
                    for (int s = 0; s < KNN; s++) {
                        float od = ds[s]; int oi = is_[s];
                        bool  pr = vd < od;
                        ds[s]  = pr ? vd : od;
                        is_[s] = pr ? vi : oi;
                        vd     = pr ? od : vd;
                        vi     = pr ? oi : vi;
                    }
                }
            }
        }

        int* op = g_idx + q * KNN;
#pragma unroll
        for (int s = 0; s < KNN; s++) op[s] = is_[s];

        if (total < KNN || bad) {
            int slot = atomicAdd(&g_wcount, 1);
            g_wlist[slot] = q;
        }
    }
}

// ---------------------------------------------------------------------------
// Fallback: BLOCK-cooperative exact scan (256 threads per flagged query) —
// unchanged (verified R9/R11).
// ---------------------------------------------------------------------------
__global__ void __launch_bounds__(256) knn_fallback(const float* __restrict__ coords) {
    __shared__ float sd[256][KNN];
    __shared__ int   sj[256][KNN];
    __shared__ float md[8 * KNN];
    __shared__ int   mj[8 * KNN];

    int tid  = threadIdx.x;
    int lane = tid & 31;
    int wid  = tid >> 5;
    int nw   = g_wcount;

    for (int w = blockIdx.x; w < nw; w += 64) {
        int q = g_wlist[w];
        int b = q >> 13, n = q & (NPTS - 1);
        const float* cb = coords + b * 3 * NPTS;
        float qx = cb[n], qy = cb[NPTS + n], qz = cb[2 * NPTS + n];
        float sqi = (qx * qx + qy * qy) + qz * qz;

        float ds[KNN];
        int   is_[KNN];
#pragma unroll
        for (int s = 0; s < KNN; s++) { ds[s] = __int_as_float(0x7f800000); is_[s] = 0x7fffffff; }

        for (int i0 = 0; i0 < 32; i0 += 8) {
            float cxs[8], cys[8], czs[8];
#pragma unroll
            for (int u = 0; u < 8; u++) {
                int j = (i0 + u) * 256 + tid;
                cxs[u] = __ldg(cb + j);
                cys[u] = __ldg(cb + NPTS + j);
                czs[u] = __ldg(cb + 2 * NPTS + j);
            }
#pragma unroll
            for (int u = 0; u < 8; u++) {
                int j = (i0 + u) * 256 + tid;
                float sq = (cxs[u] * cxs[u] + cys[u] * cys[u]) + czs[u] * czs[u];
                float inner = fmaf(qz, czs[u], fmaf(qy, cys[u], qx * cxs[u]));
                float d = fmaf(-2.0f, inner, sqi + sq);
                if (d < ds[KNN - 1]) {
                    float vd = d; int vi = j;
#pragma unroll
                    for (int s = 0; s < KNN; s++) {
                        float od = ds[s]; int oi = is_[s];
                        bool  pr = vd < od;
                        ds[s]  = pr ? vd : od;
                        is_[s] = pr ? vi : oi;
                        vd     = pr ? od : vd;
                        vi     = pr ? oi : vi;
                    }
                }
            }
        }

#pragma unroll
        for (int s = 0; s < KNN; s++) { sd[tid][s] = ds[s]; sj[tid][s] = is_[s]; }
        __syncthreads();

        {
            int ptr = 0;
            for (int k = 0; k < KNN; k++) {
                float cd = (ptr < KNN) ? sd[tid][ptr] : __int_as_float(0x7f800000);
                int   cj = (ptr < KNN) ? sj[tid][ptr] : 0x7fffffff;
                float wd = cd; int wj = cj;
#pragma unroll
                for (int off = 16; off > 0; off >>= 1) {
                    float od = __shfl_xor_sync(0xffffffffu, wd, off);
                    int   oj = __shfl_xor_sync(0xffffffffu, wj, off);
                    if (od < wd || (od == wd && oj < wj)) { wd = od; wj = oj; }
                }
                if (wd == cd && wj == cj) ptr++;
                if (lane == 0) { md[wid * KNN + k] = wd; mj[wid * KNN + k] = wj; }
            }
        }
        __syncthreads();

        if (wid == 0) {
            float fd[4]; int fj[4];
            int base = (lane >> 2) * KNN + (lane & 3) * 4;
#pragma unroll
            for (int t = 0; t < 4; t++) { fd[t] = md[base + t]; fj[t] = mj[base + t]; }
            int ptr = 0;
            for (int k = 0; k < KNN; k++) {
                float cd = (ptr < 4) ? fd[ptr] : __int_as_float(0x7f800000);
                int   cj = (ptr < 4) ? fj[ptr] : 0x7fffffff;
                float wd = cd; int wj = cj;
#pragma unroll
                for (int off = 16; off > 0; off >>= 1) {
                    float od = __shfl_xor_sync(0xffffffffu, wd, off);
                    int   oj = __shfl_xor_sync(0xffffffffu, wj, off);
                    if (od < wd || (od == wd && oj < wj)) { wd = od; wj = oj; }
                }
                if (wd == cd && wj == cj) ptr++;
                if (lane == 0) g_idx[q * KNN + k] = wj;
            }
        }
        __syncthreads();
    }
}

// ---------------------------------------------------------------------------
// GEMM: z[b][n][o] = sum_c W[o][c] * x[b][c][n]; zeroes worklist counter.
// ---------------------------------------------------------------------------
__global__ void __launch_bounds__(128) gemm_kernel(const float* __restrict__ x,
                                                   const float* __restrict__ W) {
    if (blockIdx.x == 0 && threadIdx.x == 0) g_wcount = 0;

    __shared__ float ws[COUT * CIN];
    int tid = threadIdx.x;
#pragma unroll
    for (int u = 0; u < 8; u++)
        ((float4*)ws)[tid + u * 128] = ((const float4*)W)[tid + u * 128];
    __syncthreads();

    int b     = blockIdx.x >> 7;
    int ntile = (blockIdx.x & 127) * 64;
    int nl    = tid & 63;
    int o0    = (tid >> 6) * 32;
    int n     = ntile + nl;

    const float* xb = x + b * CIN * NPTS;

    float acc[32];
#pragma unroll
    for (int i = 0; i < 32; i++) acc[i] = 0.0f;

    for (int c = 0; c < CIN; c += 4) {
        float xv0 = xb[(c + 0) * NPTS + n];
        float xv1 = xb[(c + 1) * NPTS + n];
        float xv2 = xb[(c + 2) * NPTS + n];
        float xv3 = xb[(c + 3) * NPTS + n];
#pragma unroll
        for (int i = 0; i < 32; i++) {
            float4 w4 = *(const float4*)&ws[(o0 + i) * CIN + c];
            acc[i] = fmaf(w4.x, xv0, acc[i]);
            acc[i] = fmaf(w4.y, xv1, acc[i]);
            acc[i] = fmaf(w4.z, xv2, acc[i]);
            acc[i] = fmaf(w4.w, xv3, acc[i]);
        }
    }

    float* zp = g_z + ((size_t)b * NPTS + n) * COUT + o0;
#pragma unroll
    for (int i = 0; i < 32; i += 4)
        *(float4*)&zp[i] = make_float4(acc[i], acc[i + 1], acc[i + 2], acc[i + 3]);
}

// ---------------------------------------------------------------------------
// Max-gather + coords passthrough (tail blocks).
// ---------------------------------------------------------------------------
#define MG_BLOCKS   (BB * 256)
#define CP_FLOAT4   (BB * 3 * NPTS / 4)
#define CP_BLOCKS   (CP_FLOAT4 / 256)

__global__ void __launch_bounds__(256) maxgather_kernel(float* __restrict__ y,
                                                        const float* __restrict__ coords) {
    if (blockIdx.x >= MG_BLOCKS) {
        int i = (blockIdx.x - MG_BLOCKS) * 256 + threadIdx.x;
        float4* dst = (float4*)(y + (size_t)BB * COUT * NPTS);
        dst[i] = ((const float4*)coords)[i];
        return;
    }

    __shared__ float yt[COUT][33];

    int tid = threadIdx.x;
    int w   = tid >> 5;
    int l   = tid & 31;
    int b     = blockIdx.x >> 8;
    int ntile = (blockIdx.x & 255) * 32;

    const float* zb = g_z + (size_t)b * NPTS * COUT;
    const float NEG_INF = __int_as_float(0xff800000);

    for (int qq = 0; qq < 4; qq++) {
        int nl = w * 4 + qq;
        int n  = ntile + nl;
        const int* ip = g_idx + ((size_t)b * NPTS + n) * KNN;
        float m0 = NEG_INF, m1 = NEG_INF;
#pragma unroll
        for (int k = 0; k < KNN; k++) {
            int r = __ldg(&ip[k]);
            const float* zr = zb + (size_t)r * COUT;
            m0 = fmaxf(m0, zr[l]);
            m1 = fmaxf(m1, zr[l + 32]);
        }
        yt[l][nl]      = m0;
        yt[l + 32][nl] = m1;
    }
    __syncthreads();

#pragma unroll
    for (int e = tid; e < COUT * 32; e += 256) {
        int o  = e >> 5;
        int nl = e & 31;
        y[((size_t)b * COUT + o) * NPTS + ntile + nl] = yt[o][nl];
    }
}

// ---------------------------------------------------------------------------
extern "C" void kernel_launch(void* const* d_in, const int* in_sizes, int n_in,
                              void* d_out, int out_size) {
    const float* x      = (const float*)d_in[0];
    const float* coords = (const float*)d_in[1];
    const float* W      = (const float*)d_in[2];
    float*       out    = (float*)d_out;

    gemm_kernel<<<BB * 128, 128>>>(x, W);
    knn_collect<<<NQ / QPB, 256>>>(coords);
    knn_fallback<<<64, 256>>>(coords);
    maxgather_kernel<<<MG_BLOCKS + CP_BLOCKS, 256>>>(out, coords);
}